// round 12
// baseline (speedup 1.0000x reference)
#include <cuda_runtime.h>
#include <math.h>

#define MAX_RAYS 65536
__device__ int g_seg[MAX_RAYS + 1];

typedef unsigned long long ull;

// ---- packed f32x2 helpers (Blackwell) -------------------------------------
__device__ __forceinline__ ull f2fma(ull a, ull b, ull c) {
    ull d;
    asm("fma.rn.f32x2 %0, %1, %2, %3;" : "=l"(d) : "l"(a), "l"(b), "l"(c));
    return d;
}
__device__ __forceinline__ ull f2add(ull a, ull b) {
    ull d;
    asm("add.rn.f32x2 %0, %1, %2;" : "=l"(d) : "l"(a), "l"(b));
    return d;
}
__device__ __forceinline__ ull f2pack(float lo, float hi) {
    ull d;
    asm("mov.b64 %0, {%1, %2};" : "=l"(d) : "f"(lo), "f"(hi));
    return d;
}
__device__ __forceinline__ void f2unpack(ull v, float& lo, float& hi) {
    asm("mov.b64 {%0, %1}, %2;" : "=f"(lo), "=f"(hi) : "l"(v));
}
#define ABSMASK 0x7FFFFFFF7FFFFFFFULL

// ---------------------------------------------------------------------------
// Kernel A: segment starts from sorted ray_indices; int4-vectorized.
// ---------------------------------------------------------------------------
__global__ void seg_boundary_kernel(const int* __restrict__ ri, int S, int n_rays) {
    const int q = blockIdx.x * blockDim.x + threadIdx.x;
    const int base = q * 4;
    if (base >= S) return;

    int e0, e1, e2, e3;
    if (base + 4 <= S) {
        const int4 v = *reinterpret_cast<const int4*>(ri + base);
        e0 = v.x; e1 = v.y; e2 = v.z; e3 = v.w;
    } else {
        e0 = ri[base];
        e1 = (base + 1 < S) ? ri[base + 1] : e0;
        e2 = (base + 2 < S) ? ri[base + 2] : e1;
        e3 = (base + 3 < S) ? ri[base + 3] : e2;
    }
    const int prev = (base == 0) ? -1 : ri[base - 1];

    for (int rr = prev + 1; rr <= e0; ++rr) g_seg[rr] = base;
    if (base + 1 < S) for (int rr = e0 + 1; rr <= e1; ++rr) g_seg[rr] = base + 1;
    if (base + 2 < S) for (int rr = e1 + 1; rr <= e2; ++rr) g_seg[rr] = base + 2;
    if (base + 3 < S) for (int rr = e2 + 1; rr <= e3; ++rr) g_seg[rr] = base + 3;

    if (base + 4 >= S) {
        const int lastVal = (S - 1 == base)     ? e0
                          : (S - 1 == base + 1) ? e1
                          : (S - 1 == base + 2) ? e2 : e3;
        for (int rr = lastVal + 1; rr <= n_rays; ++rr) g_seg[rr] = S;
    }
}

// ---------------------------------------------------------------------------
// Kernel B: one warp per ray. MLP collapsed to 1-D in m = ts+te:
//   acc(m) = A m + C + Sum_j sign(w2_j)|u_j m + v_j| (u=0.25 w2 d.W1, v=0.5 w2 (o.W1+b1))
// Per-ray exact m-bounds; constant-sign units folded into (A,C); active units
// compacted into per-warp pair list sQ (one LDS.128/pair).
// Main loop: 64-sample chunks, TWO CONSECUTIVE samples per lane ->
// single pair-sum warp scan per chunk + 3 boundary exps (w=E_i - E_{i+1}).
// Chunk 0's (m,dt) cached in registers from the bounds pre-pass.
// ---------------------------------------------------------------------------
__global__ void __launch_bounds__(128, 8) render_kernel(
    const float* __restrict__ rays_o,
    const float* __restrict__ rays_d,
    const float* __restrict__ W1,
    const float* __restrict__ b1,
    const float* __restrict__ W2,
    const float* __restrict__ b2,
    const float* __restrict__ t_starts,
    const float* __restrict__ t_ends,
    float* __restrict__ out,
    int n_rays)
{
    __shared__ ulonglong2 sQ[4][36];

    const int wlocal  = threadIdx.x >> 5;
    const int lane    = threadIdx.x & 31;
    const int warp_id = (blockIdx.x * blockDim.x + threadIdx.x) >> 5;
    if (warp_id >= n_rays) return;
    const int r = warp_id;

    const int start = g_seg[r];
    const int end   = g_seg[r + 1];

    if (start >= end) {                       // empty ray
        if (lane == 0) { out[2 * r] = 0.f; out[2 * r + 1] = 0.f; }
        return;
    }
    const int last = end - 1;

    const float ox = __ldg(&rays_o[3 * r    ]);
    const float oy = __ldg(&rays_o[3 * r + 1]);
    const float oz = __ldg(&rays_o[3 * r + 2]);
    const float dx = __ldg(&rays_d[3 * r    ]);
    const float dy = __ldg(&rays_d[3 * r + 1]);
    const float dz = __ldg(&rays_d[3 * r + 2]);

    // ---- pre-pass: exact m-bounds + cache chunk 0 (pair-per-lane mapping) --
    float ma = __int_as_float(0x7F800000);
    float mb = 0.f;
    float cm0, cm1, cd0, cd1;
    {
        bool first = true;
        for (int i0 = start; i0 < end; i0 += 64) {
            const int j0 = i0 + 2 * lane;
            const int k0 = min(j0, last);
            const int k1 = min(j0 + 1, last);
            const float ts0 = t_starts[k0], te0 = t_ends[k0];
            const float ts1 = t_starts[k1], te1 = t_ends[k1];
            const float m0 = ts0 + te0, m1 = ts1 + te1;
            if (first) {
                cm0 = m0; cm1 = m1; cd0 = te0 - ts0; cd1 = te1 - ts1;
                first = false;
            }
            ma = fminf(ma, fminf(m0, m1));
            mb = fmaxf(mb, fmaxf(m0, m1));
        }
        #pragma unroll
        for (int off = 16; off; off >>= 1) {
            ma = fminf(ma, __shfl_xor_sync(0xffffffffu, ma, off));
            mb = fmaxf(mb, __shfl_xor_sync(0xffffffffu, mb, off));
        }
    }

    // ---- per-ray precompute (lane handles units lane, lane+32) ------------
    float A, C;
    float u0, v0, u1, v1;
    bool act0, act1, pos0, pos1;
    {
        ull AC = 0ull;
        #pragma unroll
        for (int k = 0; k < 2; ++k) {
            const int jj = lane + 32 * k;
            const float w1x = __ldg(&W1[jj]);
            const float w1y = __ldg(&W1[64 + jj]);
            const float w1z = __ldg(&W1[128 + jj]);
            const float bb  = __ldg(&b1[jj]);
            const float w2v = __ldg(&W2[jj]);

            const float a = fmaf(dx, w1x, fmaf(dy, w1y, dz * w1z));
            const float c = fmaf(ox, w1x, fmaf(oy, w1y, fmaf(oz, w1z, bb)));
            const float u = (0.25f * w2v) * a;
            const float v = (0.5f  * w2v) * c;

            float Aadd = u, Cadd = v;

            const float ya = fmaf(u, ma, v);
            const float yb = fmaf(u, mb, v);
            const bool act = (((__float_as_uint(ya) ^ __float_as_uint(yb)) >> 31) & 1u) != 0u;
            if (!act) {
                const float f = copysignf(1.f, ya + yb) * copysignf(1.f, w2v);
                Aadd = fmaf(f, u, Aadd);
                Cadd = fmaf(f, v, Cadd);
            }
            AC = f2add(AC, f2pack(Aadd, Cadd));
            if (k == 0) { u0 = u; v0 = v; act0 = act; pos0 = (w2v >= 0.f); }
            else        { u1 = u; v1 = v; act1 = act; pos1 = (w2v >= 0.f); }
        }

        #pragma unroll
        for (int off = 16; off; off >>= 1) {
            AC = f2add(AC, __shfl_xor_sync(0xffffffffu, AC, off));
        }
        f2unpack(AC, A, C);
        C += __ldg(b2);
    }

    // ---- ballot compaction into packed pair list ---------------------------
    float* qF = (float*)sQ[wlocal];

    const unsigned bp0 = __ballot_sync(0xffffffffu, act0 && pos0);
    const unsigned bn0 = __ballot_sync(0xffffffffu, act0 && !pos0);
    const unsigned bp1 = __ballot_sync(0xffffffffu, act1 && pos1);
    const unsigned bn1 = __ballot_sync(0xffffffffu, act1 && !pos1);
    const int cP0 = __popc(bp0), cN0 = __popc(bn0);
    const int cP1 = __popc(bp1), cN1 = __popc(bn1);
    const int nPos = cP0 + cP1;
    const int nNeg = cN0 + cN1;
    const int negBase = (nPos + 1) & ~1;

    const unsigned mlt = (1u << lane) - 1u;
    if (act0) {
        const int ix = pos0 ? __popc(bp0 & mlt) : (negBase + __popc(bn0 & mlt));
        qF[4 * (ix >> 1) + (ix & 1)]     = u0;
        qF[4 * (ix >> 1) + 2 + (ix & 1)] = v0;
    }
    if (act1) {
        const int ix = pos1 ? (cP0 + __popc(bp1 & mlt))
                            : (negBase + cN0 + __popc(bn1 & mlt));
        qF[4 * (ix >> 1) + (ix & 1)]     = u1;
        qF[4 * (ix >> 1) + 2 + (ix & 1)] = v1;
    }
    if (lane == 0) {
        if (nPos & 1) {
            const int ix = nPos;
            qF[4 * (ix >> 1) + (ix & 1)]     = 0.f;
            qF[4 * (ix >> 1) + 2 + (ix & 1)] = 0.f;
        }
        if (nNeg & 1) {
            const int ix = negBase + nNeg;
            qF[4 * (ix >> 1) + (ix & 1)]     = 0.f;
            qF[4 * (ix >> 1) + 2 + (ix & 1)] = 0.f;
        }
    }
    __syncwarp();

    const int pPos      = (nPos + 1) >> 1;
    const int pNegStart = negBase >> 1;
    const int pNegEnd   = pNegStart + ((nNeg + 1) >> 1);
    const ulonglong2* qq = sQ[wlocal];

    float carry = 0.f;
    float dnum  = 0.f;    // accumulates w * m ; halved at the end
    bool  first = true;

    for (int i0 = start; i0 < end; i0 += 64) {
        const int j0 = i0 + 2 * lane;

        float m0, m1, d0, d1;
        if (first) {
            m0 = cm0; m1 = cm1; d0 = cd0; d1 = cd1;
            first = false;
        } else {
            const int k0 = min(j0, last);
            const int k1 = min(j0 + 1, last);
            const float ts0 = t_starts[k0], te0 = t_ends[k0];
            const float ts1 = t_starts[k1], te1 = t_ends[k1];
            m0 = ts0 + te0; m1 = ts1 + te1;
            d0 = te0 - ts0; d1 = te1 - ts1;
        }

        const ull m20 = f2pack(m0, m0);
        const ull m21 = f2pack(m1, m1);

        ull aP0 = 0ull, aP1 = 0ull, aN0 = 0ull, aN1 = 0ull;
        #pragma unroll 4
        for (int p = 0; p < pPos; ++p) {
            const ulonglong2 Q = qq[p];
            const ull y0 = f2fma(m20, Q.x, Q.y);
            aP0 = f2add(aP0, y0 & ABSMASK);
            const ull y1 = f2fma(m21, Q.x, Q.y);
            aP1 = f2add(aP1, y1 & ABSMASK);
        }
        #pragma unroll 4
        for (int p = pNegStart; p < pNegEnd; ++p) {
            const ulonglong2 Q = qq[p];
            const ull y0 = f2fma(m20, Q.x, Q.y);
            aN0 = f2add(aN0, y0 & ABSMASK);
            const ull y1 = f2fma(m21, Q.x, Q.y);
            aN1 = f2add(aN1, y1 & ABSMASK);
        }

        float x, y;
        f2unpack(aP0, x, y); float acc0 = x + y;
        f2unpack(aN0, x, y); acc0 -= (x + y);
        acc0 += fmaf(A, m0, C);
        f2unpack(aP1, x, y); float acc1 = x + y;
        f2unpack(aN1, x, y); acc1 -= (x + y);
        acc1 += fmaf(A, m1, C);

        const float sp0 = fmaxf(acc0, 0.f) + __logf(1.f + __expf(-fabsf(acc0)));
        const float sp1 = fmaxf(acc1, 0.f) + __logf(1.f + __expf(-fabsf(acc1)));
        const float s0 = (j0     < end) ? sp0 * d0 : 0.f;
        const float s1 = (j0 + 1 < end) ? sp1 * d1 : 0.f;

        // ---- single pair-sum scan over 64 samples --------------------------
        const float pr = s0 + s1;
        float incl = pr;
        #pragma unroll
        for (int off = 1; off < 32; off <<= 1) {
            const float xv = __shfl_up_sync(0xffffffffu, incl, off);
            if (lane >= off) incl += xv;
        }
        const float total = __shfl_sync(0xffffffffu, incl, 31);

        const float excl0 = carry + (incl - pr);
        const float excl1 = excl0 + s0;
        const float E0 = __expf(-excl0);
        const float E1 = __expf(-excl1);          // == E0 exactly when s0 == 0
        const float E2 = __expf(-(excl1 + s1));   // == E1 exactly when s1 == 0
        dnum = fmaf(E0 - E1, m0, dnum);
        dnum = fmaf(E1 - E2, m1, dnum);
        carry += total;
    }

    // only dnum needs a reduction; carry (total optical depth) is uniform
    #pragma unroll
    for (int off = 16; off; off >>= 1) {
        dnum += __shfl_xor_sync(0xffffffffu, dnum, off);
    }

    if (lane == 0) {
        const float opac  = -expm1f(-carry);
        const float depth = (0.5f * dnum) / fmaxf(opac, 1.17549435e-38f);
        out[2 * r    ] = opac;
        out[2 * r + 1] = depth;
    }
}

extern "C" void kernel_launch(void* const* d_in, const int* in_sizes, int n_in,
                              void* d_out, int out_size) {
    const float* rays_o      = (const float*)d_in[0];
    const float* rays_d      = (const float*)d_in[1];
    const float* W1          = (const float*)d_in[2];
    const float* b1          = (const float*)d_in[3];
    const float* W2          = (const float*)d_in[4];
    const float* b2          = (const float*)d_in[5];
    const float* t_starts    = (const float*)d_in[6];
    const float* t_ends      = (const float*)d_in[7];
    const int*   ray_indices = (const int*)d_in[8];

    const int S      = in_sizes[6];
    const int n_rays = in_sizes[0] / 3;

    float* out = (float*)d_out;

    const int quads = (S + 3) / 4;
    seg_boundary_kernel<<<(quads + 255) / 256, 256>>>(ray_indices, S, n_rays);

    const int warps_per_block = 4;   // 128-thread blocks
    const int blocks = (n_rays + warps_per_block - 1) / warps_per_block;
    render_kernel<<<blocks, warps_per_block * 32>>>(
        rays_o, rays_d, W1, b1, W2, b2, t_starts, t_ends, out, n_rays);
}

// round 13
// speedup vs baseline: 1.0224x; 1.0224x over previous
#include <cuda_runtime.h>
#include <math.h>

#define MAX_RAYS 65536
__device__ int g_seg[MAX_RAYS + 1];

typedef unsigned long long ull;

// ---- packed f32x2 helpers (Blackwell) -------------------------------------
__device__ __forceinline__ ull f2fma(ull a, ull b, ull c) {
    ull d;
    asm("fma.rn.f32x2 %0, %1, %2, %3;" : "=l"(d) : "l"(a), "l"(b), "l"(c));
    return d;
}
__device__ __forceinline__ ull f2add(ull a, ull b) {
    ull d;
    asm("add.rn.f32x2 %0, %1, %2;" : "=l"(d) : "l"(a), "l"(b));
    return d;
}
__device__ __forceinline__ ull f2pack(float lo, float hi) {
    ull d;
    asm("mov.b64 %0, {%1, %2};" : "=l"(d) : "f"(lo), "f"(hi));
    return d;
}
__device__ __forceinline__ void f2unpack(ull v, float& lo, float& hi) {
    asm("mov.b64 {%0, %1}, %2;" : "=f"(lo), "=f"(hi) : "l"(v));
}
#define ABSMASK 0x7FFFFFFF7FFFFFFFULL

// ---------------------------------------------------------------------------
// Kernel A: segment starts from sorted ray_indices; int4-vectorized.
// ---------------------------------------------------------------------------
__global__ void seg_boundary_kernel(const int* __restrict__ ri, int S, int n_rays) {
    const int q = blockIdx.x * blockDim.x + threadIdx.x;
    const int base = q * 4;
    if (base >= S) return;

    int e0, e1, e2, e3;
    if (base + 4 <= S) {
        const int4 v = *reinterpret_cast<const int4*>(ri + base);
        e0 = v.x; e1 = v.y; e2 = v.z; e3 = v.w;
    } else {
        e0 = ri[base];
        e1 = (base + 1 < S) ? ri[base + 1] : e0;
        e2 = (base + 2 < S) ? ri[base + 2] : e1;
        e3 = (base + 3 < S) ? ri[base + 3] : e2;
    }
    const int prev = (base == 0) ? -1 : ri[base - 1];

    for (int rr = prev + 1; rr <= e0; ++rr) g_seg[rr] = base;
    if (base + 1 < S) for (int rr = e0 + 1; rr <= e1; ++rr) g_seg[rr] = base + 1;
    if (base + 2 < S) for (int rr = e1 + 1; rr <= e2; ++rr) g_seg[rr] = base + 2;
    if (base + 3 < S) for (int rr = e2 + 1; rr <= e3; ++rr) g_seg[rr] = base + 3;

    if (base + 4 >= S) {
        const int lastVal = (S - 1 == base)     ? e0
                          : (S - 1 == base + 1) ? e1
                          : (S - 1 == base + 2) ? e2 : e3;
        for (int rr = lastVal + 1; rr <= n_rays; ++rr) g_seg[rr] = S;
    }
}

// ---------------------------------------------------------------------------
// Kernel B: one warp per ray. MLP collapsed to 1-D in m = ts+te:
//   acc(m) = A m + C + Sum_j sign(w2_j)|u_j m + v_j|
//   (u = 0.25 w2 d.W1, v = 0.5 w2 (o.W1+b1))
// Per-ray exact m-bounds; constant-sign units folded into (A,C); active units
// compacted into per-warp pair list sQ (one LDS.128/pair).
// Main loop: full 64-chunks (two consecutive samples/lane, ONE pair-sum scan,
// 3 boundary exps) while >32 samples remain; <=32 tail runs a cheap
// single-sample 32-wide path (half MLP cost).
// Opacity telescopes to 1 - exp(-total); only depth-num needs reduction.
// ---------------------------------------------------------------------------
__global__ void __launch_bounds__(128, 9) render_kernel(
    const float* __restrict__ rays_o,
    const float* __restrict__ rays_d,
    const float* __restrict__ W1,
    const float* __restrict__ b1,
    const float* __restrict__ W2,
    const float* __restrict__ b2,
    const float* __restrict__ t_starts,
    const float* __restrict__ t_ends,
    float* __restrict__ out,
    int n_rays)
{
    __shared__ ulonglong2 sQ[4][36];

    const int wlocal  = threadIdx.x >> 5;
    const int lane    = threadIdx.x & 31;
    const int warp_id = (blockIdx.x * blockDim.x + threadIdx.x) >> 5;
    if (warp_id >= n_rays) return;
    const int r = warp_id;

    const int start = g_seg[r];
    const int end   = g_seg[r + 1];

    if (start >= end) {                       // empty ray
        if (lane == 0) { out[2 * r] = 0.f; out[2 * r + 1] = 0.f; }
        return;
    }
    const int last = end - 1;

    const float ox = __ldg(&rays_o[3 * r    ]);
    const float oy = __ldg(&rays_o[3 * r + 1]);
    const float oz = __ldg(&rays_o[3 * r + 2]);
    const float dx = __ldg(&rays_d[3 * r    ]);
    const float dy = __ldg(&rays_d[3 * r + 1]);
    const float dz = __ldg(&rays_d[3 * r + 2]);

    // ---- pre-pass: exact per-ray min/max of m = ts+te ----------------------
    float ma = __int_as_float(0x7F800000);
    float mb = 0.f;
    for (int i0 = start; i0 < end; i0 += 32) {
        const int i = i0 + lane;
        if (i < end) {
            const float m = t_starts[i] + t_ends[i];
            ma = fminf(ma, m);
            mb = fmaxf(mb, m);
        }
    }
    #pragma unroll
    for (int off = 16; off; off >>= 1) {
        ma = fminf(ma, __shfl_xor_sync(0xffffffffu, ma, off));
        mb = fmaxf(mb, __shfl_xor_sync(0xffffffffu, mb, off));
    }

    // ---- per-ray precompute (lane handles units lane, lane+32) ------------
    float A, C;
    float u0, v0, u1, v1;
    bool act0, act1, pos0, pos1;
    {
        ull AC = 0ull;
        #pragma unroll
        for (int k = 0; k < 2; ++k) {
            const int jj = lane + 32 * k;
            const float w1x = __ldg(&W1[jj]);
            const float w1y = __ldg(&W1[64 + jj]);
            const float w1z = __ldg(&W1[128 + jj]);
            const float bb  = __ldg(&b1[jj]);
            const float w2v = __ldg(&W2[jj]);

            const float a = fmaf(dx, w1x, fmaf(dy, w1y, dz * w1z));
            const float c = fmaf(ox, w1x, fmaf(oy, w1y, fmaf(oz, w1z, bb)));
            const float u = (0.25f * w2v) * a;
            const float v = (0.5f  * w2v) * c;

            float Aadd = u, Cadd = v;

            const float ya = fmaf(u, ma, v);
            const float yb = fmaf(u, mb, v);
            const bool act = (((__float_as_uint(ya) ^ __float_as_uint(yb)) >> 31) & 1u) != 0u;
            if (!act) {
                const float f = copysignf(1.f, ya + yb) * copysignf(1.f, w2v);
                Aadd = fmaf(f, u, Aadd);
                Cadd = fmaf(f, v, Cadd);
            }
            AC = f2add(AC, f2pack(Aadd, Cadd));
            if (k == 0) { u0 = u; v0 = v; act0 = act; pos0 = (w2v >= 0.f); }
            else        { u1 = u; v1 = v; act1 = act; pos1 = (w2v >= 0.f); }
        }

        #pragma unroll
        for (int off = 16; off; off >>= 1) {
            AC = f2add(AC, __shfl_xor_sync(0xffffffffu, AC, off));
        }
        f2unpack(AC, A, C);
        C += __ldg(b2);
    }

    // ---- ballot compaction into packed pair list ---------------------------
    float* qF = (float*)sQ[wlocal];

    const unsigned bp0 = __ballot_sync(0xffffffffu, act0 && pos0);
    const unsigned bn0 = __ballot_sync(0xffffffffu, act0 && !pos0);
    const unsigned bp1 = __ballot_sync(0xffffffffu, act1 && pos1);
    const unsigned bn1 = __ballot_sync(0xffffffffu, act1 && !pos1);
    const int cP0 = __popc(bp0), cN0 = __popc(bn0);
    const int cP1 = __popc(bp1), cN1 = __popc(bn1);
    const int nPos = cP0 + cP1;
    const int nNeg = cN0 + cN1;
    const int negBase = (nPos + 1) & ~1;

    const unsigned mlt = (1u << lane) - 1u;
    if (act0) {
        const int ix = pos0 ? __popc(bp0 & mlt) : (negBase + __popc(bn0 & mlt));
        qF[4 * (ix >> 1) + (ix & 1)]     = u0;
        qF[4 * (ix >> 1) + 2 + (ix & 1)] = v0;
    }
    if (act1) {
        const int ix = pos1 ? (cP0 + __popc(bp1 & mlt))
                            : (negBase + cN0 + __popc(bn1 & mlt));
        qF[4 * (ix >> 1) + (ix & 1)]     = u1;
        qF[4 * (ix >> 1) + 2 + (ix & 1)] = v1;
    }
    if (lane == 0) {
        if (nPos & 1) {
            const int ix = nPos;
            qF[4 * (ix >> 1) + (ix & 1)]     = 0.f;
            qF[4 * (ix >> 1) + 2 + (ix & 1)] = 0.f;
        }
        if (nNeg & 1) {
            const int ix = negBase + nNeg;
            qF[4 * (ix >> 1) + (ix & 1)]     = 0.f;
            qF[4 * (ix >> 1) + 2 + (ix & 1)] = 0.f;
        }
    }
    __syncwarp();

    const int pPos      = (nPos + 1) >> 1;
    const int pNegStart = negBase >> 1;
    const int pNegEnd   = pNegStart + ((nNeg + 1) >> 1);
    const ulonglong2* qq = sQ[wlocal];

    float carry = 0.f;
    float dnum  = 0.f;    // accumulates w * m ; halved at the end

    // ---- full 64-chunks: two consecutive samples per lane ------------------
    int i0 = start;
    for (; end - i0 > 32; i0 += 64) {
        const int j0 = i0 + 2 * lane;
        const int k0 = min(j0, last);
        const int k1 = min(j0 + 1, last);
        const float ts0 = t_starts[k0], te0 = t_ends[k0];
        const float ts1 = t_starts[k1], te1 = t_ends[k1];
        const float m0 = ts0 + te0, m1 = ts1 + te1;
        const float d0 = te0 - ts0, d1 = te1 - ts1;

        const ull m20 = f2pack(m0, m0);
        const ull m21 = f2pack(m1, m1);

        ull aP0 = 0ull, aP1 = 0ull, aN0 = 0ull, aN1 = 0ull;
        #pragma unroll 4
        for (int p = 0; p < pPos; ++p) {
            const ulonglong2 Q = qq[p];
            const ull y0 = f2fma(m20, Q.x, Q.y);
            aP0 = f2add(aP0, y0 & ABSMASK);
            const ull y1 = f2fma(m21, Q.x, Q.y);
            aP1 = f2add(aP1, y1 & ABSMASK);
        }
        #pragma unroll 4
        for (int p = pNegStart; p < pNegEnd; ++p) {
            const ulonglong2 Q = qq[p];
            const ull y0 = f2fma(m20, Q.x, Q.y);
            aN0 = f2add(aN0, y0 & ABSMASK);
            const ull y1 = f2fma(m21, Q.x, Q.y);
            aN1 = f2add(aN1, y1 & ABSMASK);
        }

        float x, y;
        f2unpack(aP0, x, y); float acc0 = x + y;
        f2unpack(aN0, x, y); acc0 -= (x + y);
        acc0 += fmaf(A, m0, C);
        f2unpack(aP1, x, y); float acc1 = x + y;
        f2unpack(aN1, x, y); acc1 -= (x + y);
        acc1 += fmaf(A, m1, C);

        const float sp0 = fmaxf(acc0, 0.f) + __logf(1.f + __expf(-fabsf(acc0)));
        const float sp1 = fmaxf(acc1, 0.f) + __logf(1.f + __expf(-fabsf(acc1)));
        const float s0 = (j0     < end) ? sp0 * d0 : 0.f;
        const float s1 = (j0 + 1 < end) ? sp1 * d1 : 0.f;

        // single pair-sum scan over 64 samples
        const float pr = s0 + s1;
        float incl = pr;
        #pragma unroll
        for (int off = 1; off < 32; off <<= 1) {
            const float xv = __shfl_up_sync(0xffffffffu, incl, off);
            if (lane >= off) incl += xv;
        }
        const float total = __shfl_sync(0xffffffffu, incl, 31);

        const float excl0 = carry + (incl - pr);
        const float excl1 = excl0 + s0;
        const float E0 = __expf(-excl0);
        const float E1 = __expf(-excl1);
        const float E2 = __expf(-(excl1 + s1));
        dnum = fmaf(E0 - E1, m0, dnum);
        dnum = fmaf(E1 - E2, m1, dnum);
        carry += total;
    }

    // ---- tail (<=32 samples): single sample per lane -----------------------
    if (i0 < end) {
        const int k = min(i0 + lane, last);
        const float ts = t_starts[k], te = t_ends[k];
        const float m = ts + te;
        const float d = te - ts;
        const ull m2 = f2pack(m, m);

        ull aP = 0ull, aN = 0ull;
        #pragma unroll 4
        for (int p = 0; p < pPos; ++p) {
            const ull yv = f2fma(m2, qq[p].x, qq[p].y);
            aP = f2add(aP, yv & ABSMASK);
        }
        #pragma unroll 4
        for (int p = pNegStart; p < pNegEnd; ++p) {
            const ull yv = f2fma(m2, qq[p].x, qq[p].y);
            aN = f2add(aN, yv & ABSMASK);
        }
        float x, y;
        f2unpack(aP, x, y); float acc = x + y;
        f2unpack(aN, x, y); acc -= (x + y);
        acc += fmaf(A, m, C);

        const float sp = fmaxf(acc, 0.f) + __logf(1.f + __expf(-fabsf(acc)));
        const float s  = (i0 + lane < end) ? sp * d : 0.f;

        float incl = s;
        #pragma unroll
        for (int off = 1; off < 32; off <<= 1) {
            const float xv = __shfl_up_sync(0xffffffffu, incl, off);
            if (lane >= off) incl += xv;
        }
        const float excl = carry + (incl - s);
        const float E0 = __expf(-excl);
        const float E1 = __expf(-(excl + s));
        dnum = fmaf(E0 - E1, m, dnum);
        carry += __shfl_sync(0xffffffffu, incl, 31);
    }

    // only dnum needs a reduction; carry (total optical depth) is uniform
    #pragma unroll
    for (int off = 16; off; off >>= 1) {
        dnum += __shfl_xor_sync(0xffffffffu, dnum, off);
    }

    if (lane == 0) {
        const float opac  = -expm1f(-carry);
        const float depth = (0.5f * dnum) / fmaxf(opac, 1.17549435e-38f);
        out[2 * r    ] = opac;
        out[2 * r + 1] = depth;
    }
}

extern "C" void kernel_launch(void* const* d_in, const int* in_sizes, int n_in,
                              void* d_out, int out_size) {
    const float* rays_o      = (const float*)d_in[0];
    const float* rays_d      = (const float*)d_in[1];
    const float* W1          = (const float*)d_in[2];
    const float* b1          = (const float*)d_in[3];
    const float* W2          = (const float*)d_in[4];
    const float* b2          = (const float*)d_in[5];
    const float* t_starts    = (const float*)d_in[6];
    const float* t_ends      = (const float*)d_in[7];
    const int*   ray_indices = (const int*)d_in[8];

    const int S      = in_sizes[6];
    const int n_rays = in_sizes[0] / 3;

    float* out = (float*)d_out;

    const int quads = (S + 3) / 4;
    seg_boundary_kernel<<<(quads + 255) / 256, 256>>>(ray_indices, S, n_rays);

    const int warps_per_block = 4;   // 128-thread blocks
    const int blocks = (n_rays + warps_per_block - 1) / warps_per_block;
    render_kernel<<<blocks, warps_per_block * 32>>>(
        rays_o, rays_d, W1, b1, W2, b2, t_starts, t_ends, out, n_rays);
}

// round 14
// speedup vs baseline: 1.0738x; 1.0502x over previous
#include <cuda_runtime.h>
#include <math.h>

#define MAX_RAYS 65536
__device__ int g_seg[MAX_RAYS + 1];

typedef unsigned long long ull;

// ---- packed f32x2 helpers (Blackwell) -------------------------------------
__device__ __forceinline__ ull f2fma(ull a, ull b, ull c) {
    ull d;
    asm("fma.rn.f32x2 %0, %1, %2, %3;" : "=l"(d) : "l"(a), "l"(b), "l"(c));
    return d;
}
__device__ __forceinline__ ull f2add(ull a, ull b) {
    ull d;
    asm("add.rn.f32x2 %0, %1, %2;" : "=l"(d) : "l"(a), "l"(b));
    return d;
}
__device__ __forceinline__ ull f2pack(float lo, float hi) {
    ull d;
    asm("mov.b64 %0, {%1, %2};" : "=l"(d) : "f"(lo), "f"(hi));
    return d;
}
__device__ __forceinline__ void f2unpack(ull v, float& lo, float& hi) {
    asm("mov.b64 {%0, %1}, %2;" : "=f"(lo), "=f"(hi) : "l"(v));
}
#define ABSMASK 0x7FFFFFFF7FFFFFFFULL

// ---------------------------------------------------------------------------
// Kernel A: segment starts from sorted ray_indices; int4-vectorized.
// ---------------------------------------------------------------------------
__global__ void seg_boundary_kernel(const int* __restrict__ ri, int S, int n_rays) {
    const int q = blockIdx.x * blockDim.x + threadIdx.x;
    const int base = q * 4;
    if (base >= S) return;

    int e0, e1, e2, e3;
    if (base + 4 <= S) {
        const int4 v = *reinterpret_cast<const int4*>(ri + base);
        e0 = v.x; e1 = v.y; e2 = v.z; e3 = v.w;
    } else {
        e0 = ri[base];
        e1 = (base + 1 < S) ? ri[base + 1] : e0;
        e2 = (base + 2 < S) ? ri[base + 2] : e1;
        e3 = (base + 3 < S) ? ri[base + 3] : e2;
    }
    const int prev = (base == 0) ? -1 : ri[base - 1];

    for (int rr = prev + 1; rr <= e0; ++rr) g_seg[rr] = base;
    if (base + 1 < S) for (int rr = e0 + 1; rr <= e1; ++rr) g_seg[rr] = base + 1;
    if (base + 2 < S) for (int rr = e1 + 1; rr <= e2; ++rr) g_seg[rr] = base + 2;
    if (base + 3 < S) for (int rr = e2 + 1; rr <= e3; ++rr) g_seg[rr] = base + 3;

    if (base + 4 >= S) {
        const int lastVal = (S - 1 == base)     ? e0
                          : (S - 1 == base + 1) ? e1
                          : (S - 1 == base + 2) ? e2 : e3;
        for (int rr = lastVal + 1; rr <= n_rays; ++rr) g_seg[rr] = S;
    }
}

// ---------------------------------------------------------------------------
// Kernel B: TWO rays per warp (16 lanes each). MLP collapsed to 1-D in
// m = ts+te:  acc(m) = A m + C + Sum_j sign(w2_j)|u_j m + v_j|
//   (u = 0.25 w2 d.W1, v = 0.5 w2 (o.W1+b1))
// Per-ray exact m-bounds (16-lane prepass); constant-sign units folded into
// (A,C). Active units compacted per half into a 34-pair shared list:
// positives fill bottom-up, negatives top-down, zero-prefilled gap.
// Main loop: 32 samples per ray per chunk (2 consecutive/lane), 16-wide
// segmented pair-sum scan, 3 boundary exps. Opacity telescopes.
// ---------------------------------------------------------------------------
__global__ void __launch_bounds__(128, 9) render_kernel(
    const float* __restrict__ rays_o,
    const float* __restrict__ rays_d,
    const float* __restrict__ W1,
    const float* __restrict__ b1,
    const float* __restrict__ W2,
    const float* __restrict__ b2,
    const float* __restrict__ t_starts,
    const float* __restrict__ t_ends,
    float* __restrict__ out,
    int n_rays)
{
    __shared__ ulonglong2 sQ[4][2][34];   // [warp][half][pair] = {u2, v2}

    const int wlocal  = threadIdx.x >> 5;
    const int lane    = threadIdx.x & 31;
    const int half    = lane >> 4;        // which ray within the warp
    const int sl      = lane & 15;        // sub-lane within half
    const int warp_id = (blockIdx.x * blockDim.x + threadIdx.x) >> 5;
    if (2 * warp_id >= n_rays) return;

    const int  rWant    = 2 * warp_id + half;
    const bool rayValid = (rWant < n_rays);
    const int  r        = rayValid ? rWant : (n_rays - 1);

    int start = g_seg[r];
    int end   = g_seg[r + 1];
    if (!rayValid) { start = 0; end = 0; }
    const bool hasWork = (start < end);
    const int  last    = hasWork ? (end - 1) : 0;   // safe clamp index

    const float ox = __ldg(&rays_o[3 * r    ]);
    const float oy = __ldg(&rays_o[3 * r + 1]);
    const float oz = __ldg(&rays_o[3 * r + 2]);
    const float dx = __ldg(&rays_d[3 * r    ]);
    const float dy = __ldg(&rays_d[3 * r + 1]);
    const float dz = __ldg(&rays_d[3 * r + 2]);

    // ---- pre-pass: exact per-ray min/max of m = ts+te (16-lane stride) ----
    float ma = __int_as_float(0x7F800000);
    float mb = 0.f;
    for (int i0 = start; i0 < end; i0 += 16) {
        const int i = i0 + sl;
        if (i < end) {
            const float m = t_starts[i] + t_ends[i];
            ma = fminf(ma, m);
            mb = fmaxf(mb, m);
        }
    }
    #pragma unroll
    for (int off = 8; off; off >>= 1) {            // reduce within half
        ma = fminf(ma, __shfl_xor_sync(0xffffffffu, ma, off));
        mb = fmaxf(mb, __shfl_xor_sync(0xffffffffu, mb, off));
    }

    // ---- zero-prefill pair list (covers the pos/neg gap) -------------------
    #pragma unroll
    for (int z = sl; z < 34; z += 16)
        sQ[wlocal][half][z] = make_ulonglong2(0ull, 0ull);
    __syncwarp();

    // ---- per-ray precompute + incremental compaction -----------------------
    // Each half-lane handles units sl, sl+16, sl+32, sl+48 of its ray.
    float* qF = (float*)sQ[wlocal][half];
    const unsigned mlt16 = (1u << sl) - 1u;
    float A, C;
    int nPos = 0, nNeg = 0;
    {
        ull AC = 0ull;
        #pragma unroll
        for (int k = 0; k < 4; ++k) {
            const int jj = sl + 16 * k;
            const float w1x = __ldg(&W1[jj]);
            const float w1y = __ldg(&W1[64 + jj]);
            const float w1z = __ldg(&W1[128 + jj]);
            const float bb  = __ldg(&b1[jj]);
            const float w2v = __ldg(&W2[jj]);

            const float a = fmaf(dx, w1x, fmaf(dy, w1y, dz * w1z));
            const float c = fmaf(ox, w1x, fmaf(oy, w1y, fmaf(oz, w1z, bb)));
            const float u = (0.25f * w2v) * a;
            const float v = (0.5f  * w2v) * c;

            float Aadd = u, Cadd = v;

            const float ya = fmaf(u, ma, v);
            const float yb = fmaf(u, mb, v);
            bool act = (((__float_as_uint(ya) ^ __float_as_uint(yb)) >> 31) & 1u) != 0u;
            act = act && hasWork;                  // idle/empty halves: no list
            if (!act) {
                const float f = copysignf(1.f, ya + yb) * copysignf(1.f, w2v);
                Aadd = fmaf(f, u, Aadd);
                Cadd = fmaf(f, v, Cadd);
            }
            AC = f2add(AC, f2pack(Aadd, Cadd));

            const bool pos = (w2v >= 0.f);
            const unsigned bp = __ballot_sync(0xffffffffu, act && pos);
            const unsigned bn = __ballot_sync(0xffffffffu, act && !pos);
            const unsigned bpH = (bp >> (16 * half)) & 0xFFFFu;
            const unsigned bnH = (bn >> (16 * half)) & 0xFFFFu;
            if (act) {
                const int slot = pos ? (nPos + __popc(bpH & mlt16))
                                     : (67 - (nNeg + __popc(bnH & mlt16)));
                qF[4 * (slot >> 1) + (slot & 1)]     = u;
                qF[4 * (slot >> 1) + 2 + (slot & 1)] = v;
            }
            nPos += __popc(bpH);
            nNeg += __popc(bnH);
        }

        #pragma unroll
        for (int off = 8; off; off >>= 1) {        // reduce within half
            AC = f2add(AC, __shfl_xor_sync(0xffffffffu, AC, off));
        }
        f2unpack(AC, A, C);
        C += __ldg(b2);
    }
    __syncwarp();

    const int pPos      = (nPos + 1) >> 1;         // pos pairs [0, pPos)
    const int pNegStart = (68 - nNeg) >> 1;        // neg pairs [pNegStart, 34)
    const ulonglong2* qq = sQ[wlocal][half];

    float carry = 0.f;
    float dnum  = 0.f;    // accumulates w * m ; halved at the end

    for (int it = 0; ; ++it) {
        const int i0 = start + 32 * it;
        if (!__any_sync(0xffffffffu, i0 < end)) break;

        float s0 = 0.f, s1 = 0.f, m0 = 0.f, m1 = 0.f;
        if (i0 < end) {                            // uniform per half
            const int j0 = i0 + 2 * sl;
            const int k0 = min(j0, last);
            const int k1 = min(j0 + 1, last);
            const float ts0 = t_starts[k0], te0 = t_ends[k0];
            const float ts1 = t_starts[k1], te1 = t_ends[k1];
            m0 = ts0 + te0; m1 = ts1 + te1;
            const float d0 = te0 - ts0, d1 = te1 - ts1;

            const ull m20 = f2pack(m0, m0);
            const ull m21 = f2pack(m1, m1);

            ull aP0 = 0ull, aP1 = 0ull, aN0 = 0ull, aN1 = 0ull;
            #pragma unroll 4
            for (int p = 0; p < pPos; ++p) {
                const ulonglong2 Q = qq[p];
                const ull y0 = f2fma(m20, Q.x, Q.y);
                aP0 = f2add(aP0, y0 & ABSMASK);
                const ull y1 = f2fma(m21, Q.x, Q.y);
                aP1 = f2add(aP1, y1 & ABSMASK);
            }
            #pragma unroll 4
            for (int p = pNegStart; p < 34; ++p) {
                const ulonglong2 Q = qq[p];
                const ull y0 = f2fma(m20, Q.x, Q.y);
                aN0 = f2add(aN0, y0 & ABSMASK);
                const ull y1 = f2fma(m21, Q.x, Q.y);
                aN1 = f2add(aN1, y1 & ABSMASK);
            }

            float x, y;
            f2unpack(aP0, x, y); float acc0 = x + y;
            f2unpack(aN0, x, y); acc0 -= (x + y);
            acc0 += fmaf(A, m0, C);
            f2unpack(aP1, x, y); float acc1 = x + y;
            f2unpack(aN1, x, y); acc1 -= (x + y);
            acc1 += fmaf(A, m1, C);

            const float sp0 = fmaxf(acc0, 0.f) + __logf(1.f + __expf(-fabsf(acc0)));
            const float sp1 = fmaxf(acc1, 0.f) + __logf(1.f + __expf(-fabsf(acc1)));
            s0 = (j0     < end) ? sp0 * d0 : 0.f;
            s1 = (j0 + 1 < end) ? sp1 * d1 : 0.f;
        }

        // ---- 16-wide segmented pair-sum scan (both halves together) --------
        const float pr = s0 + s1;
        float incl = pr;
        #pragma unroll
        for (int off = 1; off < 16; off <<= 1) {
            const float xv = __shfl_up_sync(0xffffffffu, incl, off);
            if ((lane & 15) >= off) incl += xv;
        }
        const float total = __shfl_sync(0xffffffffu, incl, (lane & 16) | 15);

        const float excl0 = carry + (incl - pr);
        const float excl1 = excl0 + s0;
        const float E0 = __expf(-excl0);
        const float E1 = __expf(-excl1);          // == E0 exactly when s0 == 0
        const float E2 = __expf(-(excl1 + s1));   // == E1 exactly when s1 == 0
        dnum = fmaf(E0 - E1, m0, dnum);
        dnum = fmaf(E1 - E2, m1, dnum);
        carry += total;
    }

    // dnum reduction within half; carry (total optical depth) uniform per half
    #pragma unroll
    for (int off = 8; off; off >>= 1) {
        dnum += __shfl_xor_sync(0xffffffffu, dnum, off);
    }

    if (sl == 0 && rayValid) {
        const float opac  = -expm1f(-carry);
        const float depth = (0.5f * dnum) / fmaxf(opac, 1.17549435e-38f);
        out[2 * r    ] = opac;
        out[2 * r + 1] = depth;
    }
}

extern "C" void kernel_launch(void* const* d_in, const int* in_sizes, int n_in,
                              void* d_out, int out_size) {
    const float* rays_o      = (const float*)d_in[0];
    const float* rays_d      = (const float*)d_in[1];
    const float* W1          = (const float*)d_in[2];
    const float* b1          = (const float*)d_in[3];
    const float* W2          = (const float*)d_in[4];
    const float* b2          = (const float*)d_in[5];
    const float* t_starts    = (const float*)d_in[6];
    const float* t_ends      = (const float*)d_in[7];
    const int*   ray_indices = (const int*)d_in[8];

    const int S      = in_sizes[6];
    const int n_rays = in_sizes[0] / 3;

    float* out = (float*)d_out;

    const int quads = (S + 3) / 4;
    seg_boundary_kernel<<<(quads + 255) / 256, 256>>>(ray_indices, S, n_rays);

    const int warps_needed = (n_rays + 1) / 2;       // 2 rays per warp
    const int warps_per_block = 4;                   // 128-thread blocks
    const int blocks = (warps_needed + warps_per_block - 1) / warps_per_block;
    render_kernel<<<blocks, warps_per_block * 32>>>(
        rays_o, rays_d, W1, b1, W2, b2, t_starts, t_ends, out, n_rays);
}